// round 12
// baseline (speedup 1.0000x reference)
#include <cuda_runtime.h>

// QueryEncDec: 2x128-layer scalar GRU (H=in=1), T=256, fused 256-layer wavefront.
// v12 = v11 (steady-state specialization, blocking rendezvous barriers) +
// ROTATING SHUFFLE: x = shfl(val, lane-1 mod 32); lane31 pre-loads val with the
// inbox value (off-chain predicated MOV), so lane0's post-shuffle SEL is gone
// from the critical path. Lane31 owns the chunk prefetch.
//
// out[0:256]   = dec_out  (layer 255 output at each t)
// out[256:384] = dec_h    (final hidden of global layers 128..255)

#define GRU_T 256
#define NW    8
#define KC    8
#define NCH   36     // 36*8 = 288 >= 287 inner steps

__device__ __forceinline__ float ftanh(float a) {
    float r; asm("tanh.approx.f32 %0, %1;" : "=f"(r) : "f"(a)); return r;
}

struct GruW {
    float hwi_r, hwh_r, hb_r;
    float hwi_z, hwh_z, hb_z;
    float wi_n,  bi_n,  hwh_n, hbh_n;
};

template<bool STEADY>
__device__ __forceinline__ void run_chunk(
    int ic, int w, int lane, int l, bool is_prod, bool is_last,
    const float* __restrict__ inbox, float* __restrict__ outbox,
    float* __restrict__ out, const GruW& W,
    float& h, float& val, float& nc_r, float& nc_z, float& ghn_h, float& hhalf)
{
    // consumer side of rendezvous: wait for upstream t-chunk ic
    if (w > 0 && ic < GRU_T / KC) {
        asm volatile("bar.sync %0, %1;" :: "r"(w), "r"(64) : "memory");
    }
    // lane31 prefetches the 8 inbox values for this chunk
    float pf[KC];
    if (lane == 31 && ic < GRU_T / KC) {
        float4 va = *(const float4*)(inbox + ic * KC);
        float4 vb = *(const float4*)(inbox + ic * KC + 4);
        pf[0]=va.x; pf[1]=va.y; pf[2]=va.z; pf[3]=va.w;
        pf[4]=vb.x; pf[5]=vb.y; pf[6]=vb.z; pf[7]=vb.w;
    }

    const int src = (lane + 31) & 31;      // lane-1 mod 32 (lane0 <- lane31)

    #pragma unroll
    for (int u = 0; u < KC; ++u) {
        const int j = ic * KC + u;
        const int t = j - lane;

        // lane31 lends its shuffle slot to carry the inbox value (off-chain:
        // pf is chunk-resident, independent of h)
        if (lane == 31) val = pf[u];

        const float x = __shfl_sync(0xFFFFFFFFu, val, src, 32);

        const float t_r = ftanh(fmaf(W.hwi_r, x, nc_r));
        const float t_z = ftanh(fmaf(W.hwi_z, x, nc_z));
        const float xn  = fmaf(W.wi_n, x, W.bi_n);
        const float t_n = ftanh(fmaf(ghn_h, t_r, xn + ghn_h));
        const float A   = fmaf(-0.5f, t_z, 0.5f);
        const float C   = fmaf(hhalf, t_z, hhalf);
        const float hn  = fmaf(A, t_n, C);

        val = hn;                           // shuffle source for next step
        if (STEADY) {
            h = hn;                         // off the x-chain (tails only)
            if (is_prod) outbox[t] = h;
            if (is_last) out[t]    = h;     // dec_out
        } else {
            const bool valid = (t >= 0) && (t < GRU_T);
            if (valid) h = hn;
            if (is_prod && valid) outbox[t] = h;
            if (is_last && valid) out[t]    = h;                        // dec_out
            if (t == GRU_T - 1 && l >= 128) out[GRU_T + (l - 128)] = h; // dec_h
        }

        nc_r  = fmaf(W.hwh_r, h, W.hb_r);
        nc_z  = fmaf(W.hwh_z, h, W.hb_z);
        ghn_h = fmaf(W.hwh_n, h, W.hbh_n);
        hhalf = 0.5f * h;
    }

    // producer side of rendezvous: publish t-chunk ic-4 (blocking, skew-safe)
    if (w < NW - 1 && ic >= 4) {
        asm volatile("bar.sync %0, %1;" :: "r"(w + 1), "r"(64) : "memory");
    }
}

__global__ __launch_bounds__(256, 1)
void gru_wave_v12(const float* __restrict__ X,
                  const float* __restrict__ ewi, const float* __restrict__ ewh,
                  const float* __restrict__ ebi, const float* __restrict__ ebh,
                  const float* __restrict__ dwi, const float* __restrict__ dwh,
                  const float* __restrict__ dbi, const float* __restrict__ dbh,
                  float* __restrict__ out)
{
    const int tid  = threadIdx.x;
    const int l    = tid;          // global layer 0..255
    const int w    = tid >> 5;
    const int lane = tid & 31;

    __shared__ __align__(16) float xs[GRU_T];
    __shared__ __align__(16) float bb[NW - 1][GRU_T];

    if (tid < GRU_T) xs[tid] = X[tid];

    // per-layer scalar weights (torch gate order r,z,n)
    const bool  enc = (l < 128);
    const int   li  = enc ? l : (l - 128);
    const float* wi = enc ? ewi : dwi;
    const float* wh = enc ? ewh : dwh;
    const float* bi = enc ? ebi : dbi;
    const float* bh = enc ? ebh : dbh;

    const float wi_r = wi[li*3+0], wi_z = wi[li*3+1], wi_n = wi[li*3+2];
    const float wh_r = wh[li*3+0], wh_z = wh[li*3+1], wh_n = wh[li*3+2];
    const float bi_r = bi[li*3+0], bi_z = bi[li*3+1], bi_n = bi[li*3+2];
    const float bh_r = bh[li*3+0], bh_z = bh[li*3+1], bh_n = bh[li*3+2];

    GruW W;
    W.hwi_r = 0.5f * wi_r; W.hwh_r = 0.5f * wh_r; W.hb_r = 0.5f * (bi_r + bh_r);
    W.hwi_z = 0.5f * wi_z; W.hwh_z = 0.5f * wh_z; W.hb_z = 0.5f * (bi_z + bh_z);
    W.wi_n  = wi_n;        W.bi_n  = bi_n;
    W.hwh_n = 0.5f * wh_n; W.hbh_n = 0.5f * bh_n;

    float h     = 0.0f;
    float val   = 0.0f;            // shuffle source register
    float nc_r  = W.hb_r;
    float nc_z  = W.hb_z;
    float ghn_h = W.hbh_n;
    float hhalf = 0.0f;

    __syncthreads();

    const float* inbox  = (w == 0) ? xs : bb[w - 1];
    float*       outbox = (w < NW - 1) ? bb[w] : bb[0];
    const bool   is_prod = (lane == 31) && (w < NW - 1);
    const bool   is_last = (w == NW - 1) && (lane == 31);   // layer 255

    #pragma unroll 1
    for (int ic = 0; ic < 4; ++ic)
        run_chunk<false>(ic, w, lane, l, is_prod, is_last,
                         inbox, outbox, out, W, h, val, nc_r, nc_z, ghn_h, hhalf);

    #pragma unroll 1
    for (int ic = 4; ic < 31; ++ic)
        run_chunk<true>(ic, w, lane, l, is_prod, is_last,
                        inbox, outbox, out, W, h, val, nc_r, nc_z, ghn_h, hhalf);

    #pragma unroll 1
    for (int ic = 31; ic < NCH; ++ic)
        run_chunk<false>(ic, w, lane, l, is_prod, is_last,
                         inbox, outbox, out, W, h, val, nc_r, nc_z, ghn_h, hhalf);
}

extern "C" void kernel_launch(void* const* d_in, const int* in_sizes, int n_in,
                              void* d_out, int out_size)
{
    const float* X   = (const float*)d_in[0];
    const float* ewi = (const float*)d_in[1];
    const float* ewh = (const float*)d_in[2];
    const float* ebi = (const float*)d_in[3];
    const float* ebh = (const float*)d_in[4];
    const float* dwi = (const float*)d_in[5];
    const float* dwh = (const float*)d_in[6];
    const float* dbi = (const float*)d_in[7];
    const float* dbh = (const float*)d_in[8];
    float* out = (float*)d_out;

    gru_wave_v12<<<1, 256>>>(X, ewi, ewh, ebi, ebh, dwi, dwh, dbi, dbh, out);
}